// round 9
// baseline (speedup 1.0000x reference)
#include <cuda_runtime.h>
#include <cuda_bf16.h>
#include <cstdint>
#include <cstddef>

// Problem constants (fixed by the reference).
#define NN   8192   // N_NODES
#define INF  256    // IN_FEATURES
#define OUTF 32     // OUT_FEATURES

// ---------------------------------------------------------------------------
// Scratch: HW = h @ W split into bf16 hi/lo, stored transposed [plane][n][k],
// with a k-permutation applied WITHIN each 16-block so that the A operand can
// be fetched from gmem with single LDG.128 per lane per (kstep, row-half):
//   pos(k) = (k&2 ? 8 : 0) + ((k>>2)<<1) + (k&1)
// ---------------------------------------------------------------------------
__device__ __nv_bfloat16 g_B[2 * OUTF * NN];

// ---------------------------------------------------------------------------
// Kernel 1: HW = h @ W (fp32) -> hi/lo bf16 planes in g_B (permuted k).
// Also zero-initializes out (grid*block == 8192*32 elements exactly).
// ---------------------------------------------------------------------------
__global__ void __launch_bounds__(256) hw_kernel(const float* __restrict__ h,
                                                 const float* __restrict__ W,
                                                 float* __restrict__ out) {
    __shared__ float Ws[INF * OUTF];            // 32 KB, [k][n]
    const int t = threadIdx.x;
    out[blockIdx.x * 256 + t] = 0.0f;           // zero-init for atomic epilogue
    for (int i = t; i < INF * OUTF; i += 256) Ws[i] = W[i];
    __syncthreads();

    const int c   = t & 31;                     // output feature n
    const int r   = t >> 5;
    const int row = blockIdx.x * 8 + r;         // node index = k of big GEMM

    const float4* hrow = reinterpret_cast<const float4*>(h + (size_t)row * INF);
    float acc0 = 0.f, acc1 = 0.f;               // 2 chains for ILP
#pragma unroll 8
    for (int k4 = 0; k4 < INF / 4; ++k4) {
        const float4 hv = hrow[k4];
        const float* wp = &Ws[(k4 * 4) * OUTF + c];
        acc0 += hv.x * wp[0];
        acc1 += hv.y * wp[OUTF];
        acc0 += hv.z * wp[2 * OUTF];
        acc1 += hv.w * wp[3 * OUTF];
    }
    const float acc = acc0 + acc1;

    const __nv_bfloat16 hi = __float2bfloat16_rn(acc);
    const float rem        = acc - __bfloat162float(hi);
    const __nv_bfloat16 lo = __float2bfloat16_rn(rem);

    const int ph   = row & 15;
    const int p    = ((ph & 2) ? 8 : 0) | ((ph >> 2) << 1) | (ph & 1);
    const int kpos = (row & ~15) | p;
    g_B[(size_t)c * NN + kpos]          = hi;   // plane 0 (hi)
    g_B[(size_t)(OUTF + c) * NN + kpos] = lo;   // plane 1 (lo)
}

// ---------------------------------------------------------------------------
// Kernel 2: out += adj_chunk @ HW via bf16 mma.sync (hi+lo planes).
//
// Grid = 1024 CTAs: 128 m-tiles (BM=64) x 8 K-splits (1024 K each).
// CTA = 128 threads = 4 warps; warp w owns rows [w*16, w*16+16) x all n=32.
//
// A: fragments loaded DIRECTLY from gmem (2 fully-coalesced LDG.128 per lane
//    per k16), prefetch distance 1 chunk in registers.
// B: 3-stage cp.async ring (27.6 KB total), prefetch distance 2 chunks,
//    ONE __syncthreads per chunk.
// launch_bounds(128, 6): cap regs ~85 -> 6 CTAs/SM (24 warps) resident.
// Epilogue: fp32 atomicAdd into zero-initialized out.
// ---------------------------------------------------------------------------
#define BK      64
#define STAGES  3
#define PITCH   144                    // bytes per B smem row (64 halfs + pad)
#define STAGEB  (64 * PITCH)           // 9216 B per stage (2 planes x 32 n)
#define KSPLIT  8
#define KPER    (NN / KSPLIT)          // 1024
#define CH      (KPER / BK)            // 16 chunks per CTA

#define MMA_BF16(ACC, A0, A1, A2, A3, B0, B1)                                   \
    asm volatile("mma.sync.aligned.m16n8k16.row.col.f32.bf16.bf16.f32 "         \
                 "{%0,%1,%2,%3}, {%4,%5,%6,%7}, {%8,%9}, {%0,%1,%2,%3};\n"      \
                 : "+f"((ACC)[0]), "+f"((ACC)[1]), "+f"((ACC)[2]), "+f"((ACC)[3])\
                 : "r"(A0), "r"(A1), "r"(A2), "r"(A3), "r"(B0), "r"(B1))

#define LDMX4(R0, R1, R2, R3, ADDR)                                             \
    asm volatile("ldmatrix.sync.aligned.m8n8.x4.shared.b16 {%0,%1,%2,%3}, [%4];\n"\
                 : "=r"(R0), "=r"(R1), "=r"(R2), "=r"(R3) : "r"(ADDR))

__global__ void __launch_bounds__(128, 6) spmm_kernel(const float* __restrict__ adj,
                                                      float* __restrict__ out) {
    __shared__ __align__(16) char smem[STAGES * STAGEB];   // 27648 B
    const uint32_t sb0 = static_cast<uint32_t>(__cvta_generic_to_shared(smem));

    const int t    = threadIdx.x;
    const int lane = t & 31;
    const int wm   = t >> 5;                    // 4 m-warps
    const int mt   = blockIdx.x >> 3;           // m-tile 0..127
    const int ksid = blockIdx.x & 7;            // K-split id
    const int ctaM = mt * 64;
    const int kbase = ksid * KPER;

    // ---- A direct-fragment addressing: lane covers row r=lane/4 (and r+8),
    //      float4 at phys cols 4*(lane%4) within each k16 window.
    const int r  = lane >> 2;
    const int c4 = (lane & 3) << 2;
    const float* aptr = adj + (size_t)(ctaM + wm * 16 + r) * NN + kbase + c4;

    float4 pf[8];                               // prefetch: [kstep]{rows r, r+8}
    auto ld_a = [&](int chunk) {
        const float* p = aptr + chunk * BK;
#pragma unroll
        for (int ks = 0; ks < 4; ++ks) {
            pf[2 * ks]     = *reinterpret_cast<const float4*>(p + ks * 16);
            pf[2 * ks + 1] = *reinterpret_cast<const float4*>(p + ks * 16 + (size_t)8 * NN);
        }
    };

    // ---- B cp.async: 64 rows x 128B per chunk; 512 x 16B ops, 4/thread.
    auto cp_b = [&](int chunk) {
        if (chunk < CH) {
            const uint32_t bo = sb0 + (uint32_t)(chunk % STAGES) * STAGEB;
            const __nv_bfloat16* s0 = g_B + kbase + chunk * BK;
#pragma unroll
            for (int i = 0; i < 4; ++i) {
                const int idx = t + i * 128;
                const int row = idx >> 3;       // 0..63 = plane*32 + n
                const int seg = idx & 7;
                const void* src = s0 + (size_t)row * NN + seg * 8;
                const uint32_t dst = bo + row * PITCH + seg * 16;
                asm volatile("cp.async.cg.shared.global [%0], [%1], 16;\n"
                             :: "r"(dst), "l"(src));
            }
        }
        asm volatile("cp.async.commit_group;\n" ::);
    };

    // ---- B ldmatrix lane offset within a 16-row group.
    const uint32_t brow = (uint32_t)(((lane >> 4) << 3) + (lane & 7));
    const uint32_t bko  = (uint32_t)(((lane >> 3) & 1) << 4);
    const uint32_t boff = brow * PITCH + bko;

    float acc[4][4] = {};                       // 4 n8-tiles
    uint32_t cur[16];                           // chunk's packed bf16 A frags

    ld_a(0);
    cp_b(0); cp_b(1);                           // B prefetch depth 2

    for (int chunk = 0; chunk < CH; ++chunk) {
        // Convert prefetched A (frees pf for next chunk's loads).
#pragma unroll
        for (int ks = 0; ks < 4; ++ks) {
            const float4 f = pf[2 * ks], g = pf[2 * ks + 1];
            __nv_bfloat162 q0 = __floats2bfloat162_rn(f.x, f.y);   // a0
            __nv_bfloat162 q1 = __floats2bfloat162_rn(g.x, g.y);   // a1 (r+8)
            __nv_bfloat162 q2 = __floats2bfloat162_rn(f.z, f.w);   // a2
            __nv_bfloat162 q3 = __floats2bfloat162_rn(g.z, g.w);   // a3
            cur[4 * ks + 0] = *reinterpret_cast<uint32_t*>(&q0);
            cur[4 * ks + 1] = *reinterpret_cast<uint32_t*>(&q1);
            cur[4 * ks + 2] = *reinterpret_cast<uint32_t*>(&q2);
            cur[4 * ks + 3] = *reinterpret_cast<uint32_t*>(&q3);
        }
        if (chunk + 1 < CH) ld_a(chunk + 1);    // next chunk's A in flight

        asm volatile("cp.async.wait_group 1;\n" ::);   // B(chunk) arrived
        __syncthreads();                        // all warps done with chunk-1
        cp_b(chunk + 2);                        // overwrites chunk-1's stage: safe

        const uint32_t sb = sb0 + (uint32_t)(chunk % STAGES) * STAGEB;
#pragma unroll
        for (int ks = 0; ks < 4; ++ks) {
            uint32_t h0,h1,h2,h3,h4,h5,h6,h7, l0,l1,l2,l3,l4,l5,l6,l7;
            const uint32_t ko = boff + ks * 32;
            LDMX4(h0,h1,h2,h3, sb + ko);                    // hi, n0-15
            LDMX4(h4,h5,h6,h7, sb + 16 * PITCH + ko);       // hi, n16-31
            LDMX4(l0,l1,l2,l3, sb + 32 * PITCH + ko);       // lo, n0-15
            LDMX4(l4,l5,l6,l7, sb + 48 * PITCH + ko);       // lo, n16-31
            const uint32_t a0 = cur[4*ks], a1 = cur[4*ks+1],
                           a2 = cur[4*ks+2], a3 = cur[4*ks+3];
            MMA_BF16(acc[0], a0,a1,a2,a3, h0,h1);
            MMA_BF16(acc[0], a0,a1,a2,a3, l0,l1);
            MMA_BF16(acc[1], a0,a1,a2,a3, h2,h3);
            MMA_BF16(acc[1], a0,a1,a2,a3, l2,l3);
            MMA_BF16(acc[2], a0,a1,a2,a3, h4,h5);
            MMA_BF16(acc[2], a0,a1,a2,a3, l4,l5);
            MMA_BF16(acc[3], a0,a1,a2,a3, h6,h7);
            MMA_BF16(acc[3], a0,a1,a2,a3, l6,l7);
        }
    }

    // ---- Epilogue: accumulate K-split partials with fp32 atomics.
    const int row0 = ctaM + wm * 16 + (lane >> 2);
    const int col0 = (lane & 3) * 2;
#pragma unroll
    for (int tile = 0; tile < 4; ++tile) {
        float* o0 = out + (size_t)row0 * OUTF + tile * 8 + col0;
        atomicAdd(o0,                acc[tile][0]);
        atomicAdd(o0 + 1,            acc[tile][1]);
        atomicAdd(o0 + 8 * OUTF,     acc[tile][2]);
        atomicAdd(o0 + 8 * OUTF + 1, acc[tile][3]);
    }
}

// ---------------------------------------------------------------------------
// Launch: inputs: h [8192*256] f32, adj [8192*8192] f32, W [256*32] f32;
// output f32 [8192*32].
// ---------------------------------------------------------------------------
extern "C" void kernel_launch(void* const* d_in, const int* in_sizes, int n_in,
                              void* d_out, int out_size) {
    (void)in_sizes; (void)n_in; (void)out_size;
    const float* h   = reinterpret_cast<const float*>(d_in[0]);
    const float* adj = reinterpret_cast<const float*>(d_in[1]);
    const float* W   = reinterpret_cast<const float*>(d_in[2]);
    float* out       = reinterpret_cast<float*>(d_out);

    hw_kernel<<<NN / 8, 256>>>(h, W, out);                 // HW pack + out=0
    spmm_kernel<<<(NN / 64) * KSPLIT, 128>>>(adj, out);    // 1024 CTAs
}